// round 4
// baseline (speedup 1.0000x reference)
#include <cuda_runtime.h>
#include <cuda_fp16.h>
#include <cstdint>

// ---------------- problem constants ----------------
#define TOKENS 256
#define IN_F   4096
#define OUT_F  14336
#define KC     64
#define NCHUNK (IN_F / KC)        // 64
#define M_TILE 64
#define N_TILE 128
#define NTHREADS 128
#define NBLOCKS ((OUT_F / M_TILE) * (TOKENS / N_TILE))   // 224 * 2 = 448

// ---------------- scratch ----------------
__device__ __half g_xh[TOKENS * IN_F];

// ---------------- smem layout (per CTA) ----------------
// per stage (128B rows): W 64x128B = 8192 | x 128x128B = 16384
#define STAGE_BYTES 24576
#define SM_W(s)     ((s) * STAGE_BYTES)
#define SM_X(s)     (SM_W(s) + 8192)
#define SMEM_TOTAL  (2 * STAGE_BYTES)   // 49152 B

// ---------------- helpers ----------------
__device__ __forceinline__ uint32_t smem_u32(const void* p) {
    uint32_t a;
    asm("{ .reg .u64 t; cvta.to.shared.u64 t, %1; cvt.u32.u64 %0, t; }" : "=r"(a) : "l"(p));
    return a;
}

// 128B-row swizzle: XOR bits[6:4] with bits[9:7]
__device__ __forceinline__ uint32_t sw128(uint32_t off) {
    return off ^ ((off >> 3) & 0x70);
}

__device__ __forceinline__ void cp_async16(uint32_t dst, const void* src) {
    asm volatile("cp.async.cg.shared.global [%0], [%1], 16;" :: "r"(dst), "l"(src));
}
#define CP_COMMIT()  asm volatile("cp.async.commit_group;" ::: "memory")
#define CP_WAIT0()   asm volatile("cp.async.wait_group 0;" ::: "memory")

#define LDSM4(R, addr)                                                              \
    asm volatile("ldmatrix.sync.aligned.m8n8.x4.shared.b16 {%0,%1,%2,%3}, [%4];"    \
        : "=r"((R)[0]), "=r"((R)[1]), "=r"((R)[2]), "=r"((R)[3]) : "r"(addr))

#define MMA16816(C, A, B0, B1)                                                      \
    asm volatile("mma.sync.aligned.m16n8k16.row.col.f32.f16.f16.f32 "               \
        "{%0,%1,%2,%3}, {%4,%5,%6,%7}, {%8,%9}, {%0,%1,%2,%3};"                     \
        : "+f"((C)[0]), "+f"((C)[1]), "+f"((C)[2]), "+f"((C)[3])                    \
        : "r"((A)[0]), "r"((A)[1]), "r"((A)[2]), "r"((A)[3]), "r"(B0), "r"(B1))

// ---------------- prep: x -> fp16 ----------------
__global__ void prep_half_kernel(const float* __restrict__ x) {
    int i = blockIdx.x * blockDim.x + threadIdx.x;
    float2 v = ((const float2*)x)[i];
    __half2 h;
    h.x = __float2half_rn(v.x);
    h.y = __float2half_rn(v.y);
    ((__half2*)g_xh)[i] = h;
}

// ---------------- main GEMM kernel ----------------
__global__ void __launch_bounds__(NTHREADS, 4)
qlinear_kernel(const int* __restrict__ qw, const float* __restrict__ scale,
               const float* __restrict__ bias, float* __restrict__ out) {
    extern __shared__ char smem[];
    const uint32_t sb = smem_u32(smem);
    const int tid  = threadIdx.x;
    const int lane = tid & 31;
    const int wid  = tid >> 5;        // 0..3
    const int wm   = wid & 1;         // 2 warps along M (32 rows each)
    const int wn   = wid >> 1;        // 2 warps along N (64 tokens each)
    const int mtile = blockIdx.x >> 1;
    const int ntile = blockIdx.x & 1;
    const int out0 = mtile * M_TILE;
    const int tok0_cta = ntile * N_TILE;

    // ---- W loader: thread t -> row t/2 (0..63), ints [(t&1)*32, +32) of chunk ----
    const int wrow = tid >> 1;
    const int wq   = tid & 1;                 // which 32-int half
    const int4* wptr = (const int4*)(qw + (size_t)(out0 + wrow) * IN_F + wq * 32);
    uint32_t w_sts[2];
    w_sts[0] = sw128((uint32_t)wrow * 128 + (uint32_t)wq * 64);
    w_sts[1] = sw128((uint32_t)wrow * 128 + (uint32_t)wq * 64 + 32);
    // each 32-B STS region needs two v4 stores 16B apart (swizzle-safe: same 16B unit granularity)
    uint32_t w_sts_b[2];
    w_sts_b[0] = sw128((uint32_t)wrow * 128 + (uint32_t)wq * 64 + 16);
    w_sts_b[1] = sw128((uint32_t)wrow * 128 + (uint32_t)wq * 64 + 48);

    const char* xh_b = (const char*)g_xh + (size_t)tok0_cta * (IN_F * 2);

    // ---- ldmatrix base indices ----
    const int aRow = wm * 32 + (lane & 15);
    const int aKs  = (lane & 16) ? 16 : 0;
    const int bRow = wn * 64 + (lane & 7) + ((lane & 16) ? 8 : 0);
    const int bKs  = (lane & 8) ? 16 : 0;

    float acc[2][8][4];
    #pragma unroll
    for (int i = 0; i < 2; i++)
        #pragma unroll
        for (int j = 0; j < 8; j++)
            #pragma unroll
            for (int k = 0; k < 4; k++) acc[i][j][k] = 0.0f;

    // ---- prologue: x chunk0 -> stage0 (128 rows x 128B = 1024 x 16B units) ----
    {
        #pragma unroll
        for (int j = 0; j < 8; j++) {
            int u = tid + j * NTHREADS;          // 0..1023
            int row = u >> 3, c = u & 7;
            uint32_t d = sw128((uint32_t)row * 128 + (uint32_t)c * 16);
            size_t so = (size_t)row * (IN_F * 2) + (size_t)c * 16;
            cp_async16(sb + SM_X(0) + d, xh_b + so);
        }
        CP_COMMIT();
    }
    int4 v[8];
    #pragma unroll
    for (int j = 0; j < 8; j++) v[j] = wptr[j];

    for (int i = 0; i < NCHUNK; i++) {
        const int s = i & 1;
        const uint32_t sw_base = sb + SM_W(s);
        const uint32_t sx_base = sb + SM_X(s);

        // 1. convert + STS W chunk i (32 ints -> 32 halves = 64B)
        {
            #pragma unroll
            for (int g = 0; g < 2; g++) {
                __half2 h[8];
                #pragma unroll
                for (int q = 0; q < 4; q++) {
                    int4 a = v[g * 4 + q];
                    h[2 * q]     = __halves2half2(__int2half_rn(a.x), __int2half_rn(a.y));
                    h[2 * q + 1] = __halves2half2(__int2half_rn(a.z), __int2half_rn(a.w));
                }
                uint32_t* p = (uint32_t*)h;
                asm volatile("st.shared.v4.b32 [%0], {%1,%2,%3,%4};"
                             :: "r"(sw_base + w_sts[g]), "r"(p[0]), "r"(p[1]), "r"(p[2]), "r"(p[3]) : "memory");
                asm volatile("st.shared.v4.b32 [%0], {%1,%2,%3,%4};"
                             :: "r"(sw_base + w_sts_b[g]), "r"(p[4]), "r"(p[5]), "r"(p[6]), "r"(p[7]) : "memory");
            }
        }

        // 2. wait x chunk i, make stage visible
        CP_WAIT0();
        __syncthreads();

        // 3. prefetch chunk i+1
        if (i + 1 < NCHUNK) {
            const int sn = s ^ 1;
            const size_t co = (size_t)(i + 1) * (KC * 2);
            #pragma unroll
            for (int j = 0; j < 8; j++) {
                int u = tid + j * NTHREADS;
                int row = u >> 3, c = u & 7;
                uint32_t d = sw128((uint32_t)row * 128 + (uint32_t)c * 16);
                size_t so = (size_t)row * (IN_F * 2) + co + (size_t)c * 16;
                cp_async16(sb + SM_X(sn) + d, xh_b + so);
            }
            CP_COMMIT();
            const int4* wnp = wptr + (size_t)(i + 1) * 16;
            #pragma unroll
            for (int j = 0; j < 8; j++) v[j] = wnp[j];
        }

        // 4. compute chunk i: 4 k16 steps
        #pragma unroll
        for (int ks = 0; ks < 4; ks++) {
            const uint32_t kb = (uint32_t)ks * 32;
            uint32_t a[2][4];
            #pragma unroll
            for (int fm = 0; fm < 2; fm++)
                LDSM4(a[fm], sw_base + sw128((uint32_t)(aRow + fm * 16) * 128 + kb + aKs));

            uint32_t b[4][4];
            #pragma unroll
            for (int fn = 0; fn < 4; fn++)
                LDSM4(b[fn], sx_base + sw128((uint32_t)(bRow + fn * 16) * 128 + kb + bKs));
            #pragma unroll
            for (int fm = 0; fm < 2; fm++)
                #pragma unroll
                for (int fn = 0; fn < 4; fn++) {
                    MMA16816(acc[fm][2 * fn],     a[fm], b[fn][0], b[fn][1]);
                    MMA16816(acc[fm][2 * fn + 1], a[fm], b[fn][2], b[fn][3]);
                }
        }
    }

    // ---- epilogue: fuse scale + bias ----
    const int m_base = out0 + wm * 32 + (lane >> 2);
    #pragma unroll
    for (int fm = 0; fm < 2; fm++) {
        const int m0 = m_base + fm * 16;
        const float s0 = scale[m0],     bi0 = bias[m0];
        const float s1 = scale[m0 + 8], bi1 = bias[m0 + 8];
        #pragma unroll
        for (int nf = 0; nf < 8; nf++) {
            const int t0 = tok0_cta + wn * 64 + nf * 8 + (lane & 3) * 2;
            float* o = out + (size_t)t0 * OUT_F;
            o[m0]             = fmaf(acc[fm][nf][0], s0, bi0);
            o[OUT_F + m0]     = fmaf(acc[fm][nf][1], s0, bi0);
            o[m0 + 8]         = fmaf(acc[fm][nf][2], s1, bi1);
            o[OUT_F + m0 + 8] = fmaf(acc[fm][nf][3], s1, bi1);
        }
    }
}

// ---------------- launch ----------------
extern "C" void kernel_launch(void* const* d_in, const int* in_sizes, int n_in,
                              void* d_out, int out_size) {
    const float* x     = (const float*)d_in[0];
    const int*   qw    = (const int*)d_in[1];
    const float* scale = (const float*)d_in[2];
    const float* bias  = (const float*)d_in[3];
    float* out = (float*)d_out;

    prep_half_kernel<<<(TOKENS * IN_F / 2) / 256, 256>>>(x);

    cudaFuncSetAttribute(qlinear_kernel, cudaFuncAttributeMaxDynamicSharedMemorySize, SMEM_TOTAL);
    qlinear_kernel<<<NBLOCKS, NTHREADS, SMEM_TOTAL>>>(qw, scale, bias, out);
}

// round 5
// speedup vs baseline: 1.9742x; 1.9742x over previous
#include <cuda_runtime.h>
#include <cuda_fp16.h>
#include <cstdint>

// ---------------- problem constants ----------------
#define TOKENS 256
#define IN_F   4096
#define OUT_F  14336
#define KC     64
#define NCHUNK (IN_F / KC)        // 64
#define M_TILE 64
#define NTHREADS 256
#define NBLOCKS (OUT_F / M_TILE)  // 224

// ---------------- scratch ----------------
__device__ __half g_xh[TOKENS * IN_F];

// ---------------- smem layout (per CTA) ----------------
// per stage (128B rows): W 64x128B = 8192 | x 256x128B = 32768
#define STAGE_BYTES 40960
#define SM_W(s)     ((s) * STAGE_BYTES)
#define SM_X(s)     (SM_W(s) + 8192)
#define SMEM_TOTAL  (2 * STAGE_BYTES)   // 81920 B -> 2 CTAs/SM

// ---------------- helpers ----------------
__device__ __forceinline__ uint32_t smem_u32(const void* p) {
    uint32_t a;
    asm("{ .reg .u64 t; cvta.to.shared.u64 t, %1; cvt.u32.u64 %0, t; }" : "=r"(a) : "l"(p));
    return a;
}

// 128B-row swizzle: XOR bits[6:4] with bits[9:7]
__device__ __forceinline__ uint32_t sw128(uint32_t off) {
    return off ^ ((off >> 3) & 0x70);
}

__device__ __forceinline__ void cp_async16(uint32_t dst, const void* src) {
    asm volatile("cp.async.cg.shared.global [%0], [%1], 16;" :: "r"(dst), "l"(src));
}
#define CP_COMMIT()  asm volatile("cp.async.commit_group;" ::: "memory")
#define CP_WAIT0()   asm volatile("cp.async.wait_group 0;" ::: "memory")

#define LDSM4(R, addr)                                                              \
    asm volatile("ldmatrix.sync.aligned.m8n8.x4.shared.b16 {%0,%1,%2,%3}, [%4];"    \
        : "=r"((R)[0]), "=r"((R)[1]), "=r"((R)[2]), "=r"((R)[3]) : "r"(addr))

#define MMA16816(C, A, B0, B1)                                                      \
    asm volatile("mma.sync.aligned.m16n8k16.row.col.f32.f16.f16.f32 "               \
        "{%0,%1,%2,%3}, {%4,%5,%6,%7}, {%8,%9}, {%0,%1,%2,%3};"                     \
        : "+f"((C)[0]), "+f"((C)[1]), "+f"((C)[2]), "+f"((C)[3])                    \
        : "r"((A)[0]), "r"((A)[1]), "r"((A)[2]), "r"((A)[3]), "r"(B0), "r"(B1))

// ---------------- prep: x -> fp16 ----------------
__global__ void prep_half_kernel(const float* __restrict__ x) {
    int i = blockIdx.x * blockDim.x + threadIdx.x;
    float2 v = ((const float2*)x)[i];
    __half2 h;
    h.x = __float2half_rn(v.x);
    h.y = __float2half_rn(v.y);
    ((__half2*)g_xh)[i] = h;
}

// ---------------- main GEMM kernel ----------------
__global__ void __launch_bounds__(NTHREADS, 2)
qlinear_kernel(const int* __restrict__ qw, const float* __restrict__ scale,
               const float* __restrict__ bias, float* __restrict__ out) {
    extern __shared__ char smem[];
    const uint32_t sb = smem_u32(smem);
    const int tid  = threadIdx.x;
    const int lane = tid & 31;
    const int wid  = tid >> 5;        // 0..7
    const int wm   = wid & 1;         // 2 warps along M (32 rows each)
    const int wn   = wid >> 1;        // 4 warps along N (64 tokens each)
    const int out0 = blockIdx.x * M_TILE;

    // ---- W loader: thread t -> row t/4 (0..63), ints [16q, 16q+16) of each chunk ----
    const int wrow = tid >> 2;
    const int wq   = tid & 3;
    const int4* wptr = (const int4*)(qw + (size_t)(out0 + wrow) * IN_F + wq * 16);
    const uint32_t w_sts0 = sw128((uint32_t)wrow * 128 + (uint32_t)wq * 32);
    const uint32_t w_sts1 = sw128((uint32_t)wrow * 128 + (uint32_t)wq * 32 + 16);

    const char* xh_b = (const char*)g_xh;

    // ---- ldmatrix base indices ----
    const int aRow = wm * 32 + (lane & 15);
    const int aKs  = (lane & 16) ? 16 : 0;
    const int bRow = wn * 64 + (lane & 7) + ((lane & 16) ? 8 : 0);
    const int bKs  = (lane & 8) ? 16 : 0;

    float acc[2][8][4];
    #pragma unroll
    for (int i = 0; i < 2; i++)
        #pragma unroll
        for (int j = 0; j < 8; j++)
            #pragma unroll
            for (int k = 0; k < 4; k++) acc[i][j][k] = 0.0f;

    // ---- prologue: x chunk0 -> stage0 (256 rows x 128B = 2048 x 16B units) ----
    {
        #pragma unroll
        for (int j = 0; j < 8; j++) {
            int u = tid + j * NTHREADS;          // 0..2047
            int row = u >> 3, c = u & 7;
            uint32_t d = sw128((uint32_t)row * 128 + (uint32_t)c * 16);
            size_t so = (size_t)row * (IN_F * 2) + (size_t)c * 16;
            cp_async16(sb + SM_X(0) + d, xh_b + so);
        }
        CP_COMMIT();
    }
    int4 v0 = wptr[0], v1 = wptr[1], v2 = wptr[2], v3 = wptr[3];

    for (int i = 0; i < NCHUNK; i++) {
        const int s = i & 1;
        const uint32_t sw_base = sb + SM_W(s);
        const uint32_t sx_base = sb + SM_X(s);

        // 1. convert + STS W chunk i (16 ints -> 16 halves = 32B)
        {
            __half2 h[8];
            h[0] = __halves2half2(__int2half_rn(v0.x), __int2half_rn(v0.y));
            h[1] = __halves2half2(__int2half_rn(v0.z), __int2half_rn(v0.w));
            h[2] = __halves2half2(__int2half_rn(v1.x), __int2half_rn(v1.y));
            h[3] = __halves2half2(__int2half_rn(v1.z), __int2half_rn(v1.w));
            h[4] = __halves2half2(__int2half_rn(v2.x), __int2half_rn(v2.y));
            h[5] = __halves2half2(__int2half_rn(v2.z), __int2half_rn(v2.w));
            h[6] = __halves2half2(__int2half_rn(v3.x), __int2half_rn(v3.y));
            h[7] = __halves2half2(__int2half_rn(v3.z), __int2half_rn(v3.w));
            uint32_t* p = (uint32_t*)h;
            asm volatile("st.shared.v4.b32 [%0], {%1,%2,%3,%4};"
                         :: "r"(sw_base + w_sts0), "r"(p[0]), "r"(p[1]), "r"(p[2]), "r"(p[3]) : "memory");
            asm volatile("st.shared.v4.b32 [%0], {%1,%2,%3,%4};"
                         :: "r"(sw_base + w_sts1), "r"(p[4]), "r"(p[5]), "r"(p[6]), "r"(p[7]) : "memory");
        }

        // 2. wait x chunk i, make stage visible
        CP_WAIT0();
        __syncthreads();

        // 3. prefetch chunk i+1
        if (i + 1 < NCHUNK) {
            const int sn = s ^ 1;
            const size_t co = (size_t)(i + 1) * (KC * 2);
            #pragma unroll
            for (int j = 0; j < 8; j++) {
                int u = tid + j * NTHREADS;
                int row = u >> 3, c = u & 7;
                uint32_t d = sw128((uint32_t)row * 128 + (uint32_t)c * 16);
                size_t so = (size_t)row * (IN_F * 2) + co + (size_t)c * 16;
                cp_async16(sb + SM_X(sn) + d, xh_b + so);
            }
            CP_COMMIT();
            const int4* wnp = wptr + (size_t)(i + 1) * 16;
            v0 = wnp[0]; v1 = wnp[1]; v2 = wnp[2]; v3 = wnp[3];
        }

        // 4. compute chunk i: 4 k16 steps
        #pragma unroll
        for (int ks = 0; ks < 4; ks++) {
            const uint32_t kb = (uint32_t)ks * 32;
            uint32_t a[2][4];
            #pragma unroll
            for (int fm = 0; fm < 2; fm++)
                LDSM4(a[fm], sw_base + sw128((uint32_t)(aRow + fm * 16) * 128 + kb + aKs));

            uint32_t b[4][4];
            #pragma unroll
            for (int fn = 0; fn < 4; fn++)
                LDSM4(b[fn], sx_base + sw128((uint32_t)(bRow + fn * 16) * 128 + kb + bKs));
            #pragma unroll
            for (int fm = 0; fm < 2; fm++)
                #pragma unroll
                for (int fn = 0; fn < 4; fn++) {
                    MMA16816(acc[fm][2 * fn],     a[fm], b[fn][0], b[fn][1]);
                    MMA16816(acc[fm][2 * fn + 1], a[fm], b[fn][2], b[fn][3]);
                }
        }
    }

    // ---- epilogue: fuse scale + bias ----
    const int m_base = out0 + wm * 32 + (lane >> 2);
    #pragma unroll
    for (int fm = 0; fm < 2; fm++) {
        const int m0 = m_base + fm * 16;
        const float s0 = scale[m0],     bi0 = bias[m0];
        const float s1 = scale[m0 + 8], bi1 = bias[m0 + 8];
        #pragma unroll
        for (int nf = 0; nf < 8; nf++) {
            const int t0 = wn * 64 + nf * 8 + (lane & 3) * 2;
            float* o = out + (size_t)t0 * OUT_F;
            o[m0]             = fmaf(acc[fm][nf][0], s0, bi0);
            o[OUT_F + m0]     = fmaf(acc[fm][nf][1], s0, bi0);
            o[m0 + 8]         = fmaf(acc[fm][nf][2], s1, bi1);
            o[OUT_F + m0 + 8] = fmaf(acc[fm][nf][3], s1, bi1);
        }
    }
}

// ---------------- launch ----------------
extern "C" void kernel_launch(void* const* d_in, const int* in_sizes, int n_in,
                              void* d_out, int out_size) {
    const float* x     = (const float*)d_in[0];
    const int*   qw    = (const int*)d_in[1];
    const float* scale = (const float*)d_in[2];
    const float* bias  = (const float*)d_in[3];
    float* out = (float*)d_out;

    prep_half_kernel<<<(TOKENS * IN_F / 2) / 256, 256>>>(x);

    cudaFuncSetAttribute(qlinear_kernel, cudaFuncAttributeMaxDynamicSharedMemorySize, SMEM_TOTAL);
    qlinear_kernel<<<NBLOCKS, NTHREADS, SMEM_TOTAL>>>(qw, scale, bias, out);
}

// round 6
// speedup vs baseline: 2.0733x; 1.0502x over previous
#include <cuda_runtime.h>
#include <cuda_fp16.h>
#include <cstdint>

// ---------------- problem constants ----------------
#define TOKENS 256
#define IN_F   4096
#define OUT_F  14336
#define KC     64
#define NCHUNK (IN_F / KC)        // 64
#define M_TILE 128
#define NTHREADS 512
#define NBLOCKS (OUT_F / M_TILE)  // 112

// ---------------- scratch ----------------
__device__ __half g_xh[TOKENS * IN_F];

// ---------------- smem layout ----------------
// per stage (128B rows): W 128x128B = 16384 | x 256x128B = 32768
#define STAGE_BYTES 49152
#define SM_W(s)     ((s) * STAGE_BYTES)
#define SM_X(s)     (SM_W(s) + 16384)
#define SMEM_TOTAL  (2 * STAGE_BYTES)   // 98304 B

// ---------------- helpers ----------------
__device__ __forceinline__ uint32_t smem_u32(const void* p) {
    uint32_t a;
    asm("{ .reg .u64 t; cvta.to.shared.u64 t, %1; cvt.u32.u64 %0, t; }" : "=r"(a) : "l"(p));
    return a;
}

// 128B-row swizzle: XOR bits[6:4] with bits[9:7]
__device__ __forceinline__ uint32_t sw128(uint32_t off) {
    return off ^ ((off >> 3) & 0x70);
}

__device__ __forceinline__ void cp_async16(uint32_t dst, const void* src) {
    asm volatile("cp.async.cg.shared.global [%0], [%1], 16;" :: "r"(dst), "l"(src));
}
#define CP_COMMIT()  asm volatile("cp.async.commit_group;" ::: "memory")
#define CP_WAIT0()   asm volatile("cp.async.wait_group 0;" ::: "memory")

#define LDSM4(R, addr)                                                              \
    asm volatile("ldmatrix.sync.aligned.m8n8.x4.shared.b16 {%0,%1,%2,%3}, [%4];"    \
        : "=r"((R)[0]), "=r"((R)[1]), "=r"((R)[2]), "=r"((R)[3]) : "r"(addr))

#define MMA16816(C, A, B0, B1)                                                      \
    asm volatile("mma.sync.aligned.m16n8k16.row.col.f32.f16.f16.f32 "               \
        "{%0,%1,%2,%3}, {%4,%5,%6,%7}, {%8,%9}, {%0,%1,%2,%3};"                     \
        : "+f"((C)[0]), "+f"((C)[1]), "+f"((C)[2]), "+f"((C)[3])                    \
        : "r"((A)[0]), "r"((A)[1]), "r"((A)[2]), "r"((A)[3]), "r"(B0), "r"(B1))

// ---------------- prep: x -> fp16 ----------------
__global__ void prep_half_kernel(const float* __restrict__ x) {
    int i = blockIdx.x * blockDim.x + threadIdx.x;
    float2 v = ((const float2*)x)[i];
    __half2 h;
    h.x = __float2half_rn(v.x);
    h.y = __float2half_rn(v.y);
    ((__half2*)g_xh)[i] = h;
}

// ---------------- main GEMM kernel ----------------
__global__ void __launch_bounds__(NTHREADS, 1)
qlinear_kernel(const int* __restrict__ qw, const float* __restrict__ scale,
               const float* __restrict__ bias, float* __restrict__ out) {
    extern __shared__ char smem[];
    const uint32_t sb = smem_u32(smem);
    const int tid  = threadIdx.x;
    const int lane = tid & 31;
    const int wid  = tid >> 5;
    const int wm   = wid & 3;   // 4 warps along M (32 rows each)
    const int wn   = wid >> 2;  // 4 warps along N (64 tokens each)
    const int ko   = wid >> 2;  // kstep stagger: SMSP-mates get distinct offsets
    const int out0 = blockIdx.x * M_TILE;

    // ---- W loader: thread t -> row t/4, ints [16q, 16q+16) of each chunk ----
    const int wrow = tid >> 2;      // 0..127
    const int wq   = tid & 3;
    const int4* wptr = (const int4*)(qw + (size_t)(out0 + wrow) * IN_F + wq * 16);
    const uint32_t w_sts0 = sw128((uint32_t)wrow * 128 + (uint32_t)wq * 32);
    const uint32_t w_sts1 = sw128((uint32_t)wrow * 128 + (uint32_t)wq * 32 + 16);

    const char* xh_b = (const char*)g_xh;

    // ---- ldmatrix base indices ----
    const int aRow = wm * 32 + (lane & 15);
    const int aKs  = (lane & 16) ? 16 : 0;
    const int bRow = wn * 64 + (lane & 7) + ((lane & 16) ? 8 : 0);
    const int bKs  = (lane & 8) ? 16 : 0;

    float acc[2][8][4];
    #pragma unroll
    for (int i = 0; i < 2; i++)
        #pragma unroll
        for (int j = 0; j < 8; j++)
            #pragma unroll
            for (int k = 0; k < 4; k++) acc[i][j][k] = 0.0f;

    // ---- prologue: x chunk0 -> stage0 ----
    {
        #pragma unroll
        for (int j = 0; j < 4; j++) {
            int u = tid + j * NTHREADS;          // 0..2047
            int row = u >> 3, c = u & 7;
            uint32_t d = sw128((uint32_t)row * 128 + (uint32_t)c * 16);
            size_t so = (size_t)row * (IN_F * 2) + (size_t)c * 16;
            cp_async16(sb + SM_X(0) + d, xh_b + so);
        }
        CP_COMMIT();
    }
    int4 v0 = wptr[0], v1 = wptr[1], v2 = wptr[2], v3 = wptr[3];

    for (int i = 0; i < NCHUNK; i++) {
        const int s = i & 1;
        const uint32_t sw_base = sb + SM_W(s);
        const uint32_t sx_base = sb + SM_X(s);

        // 1. convert + STS W chunk i (16 ints -> 16 halves)
        {
            __half2 h[8];
            h[0] = __halves2half2(__int2half_rn(v0.x), __int2half_rn(v0.y));
            h[1] = __halves2half2(__int2half_rn(v0.z), __int2half_rn(v0.w));
            h[2] = __halves2half2(__int2half_rn(v1.x), __int2half_rn(v1.y));
            h[3] = __halves2half2(__int2half_rn(v1.z), __int2half_rn(v1.w));
            h[4] = __halves2half2(__int2half_rn(v2.x), __int2half_rn(v2.y));
            h[5] = __halves2half2(__int2half_rn(v2.z), __int2half_rn(v2.w));
            h[6] = __halves2half2(__int2half_rn(v3.x), __int2half_rn(v3.y));
            h[7] = __halves2half2(__int2half_rn(v3.z), __int2half_rn(v3.w));
            uint32_t* p = (uint32_t*)h;
            asm volatile("st.shared.v4.b32 [%0], {%1,%2,%3,%4};"
                         :: "r"(sw_base + w_sts0), "r"(p[0]), "r"(p[1]), "r"(p[2]), "r"(p[3]) : "memory");
            asm volatile("st.shared.v4.b32 [%0], {%1,%2,%3,%4};"
                         :: "r"(sw_base + w_sts1), "r"(p[4]), "r"(p[5]), "r"(p[6]), "r"(p[7]) : "memory");
        }

        // 2. wait x chunk i, make stage visible
        CP_WAIT0();
        __syncthreads();

        // 3. prefetch chunk i+1
        if (i + 1 < NCHUNK) {
            const int sn = s ^ 1;
            const size_t co = (size_t)(i + 1) * (KC * 2);
            #pragma unroll
            for (int j = 0; j < 4; j++) {
                int u = tid + j * NTHREADS;
                int row = u >> 3, c = u & 7;
                uint32_t d = sw128((uint32_t)row * 128 + (uint32_t)c * 16);
                size_t so = (size_t)row * (IN_F * 2) + co + (size_t)c * 16;
                cp_async16(sb + SM_X(sn) + d, xh_b + so);
            }
            CP_COMMIT();
            const int4* wnp = wptr + (size_t)(i + 1) * 16;
            v0 = wnp[0]; v1 = wnp[1]; v2 = wnp[2]; v3 = wnp[3];
        }

        // 4. compute chunk i: 4 k16 steps, STAGGERED start per SMSP-mate.
        //    Warps w, w+4, w+8, w+12 share an SMSP; ko = wid>>2 gives them
        //    rotations 0123/1230/2301/3012 so LDSM and MMA phases of
        //    co-resident warps overlap instead of aligning.
        #pragma unroll
        for (int kk = 0; kk < 4; kk++) {
            const int ks = (kk + ko) & 3;
            const uint32_t kb = (uint32_t)ks * 32;
            uint32_t a[2][4];
            #pragma unroll
            for (int fm = 0; fm < 2; fm++)
                LDSM4(a[fm], sw_base + sw128((uint32_t)(aRow + fm * 16) * 128 + kb + aKs));

            uint32_t b[4][4];
            #pragma unroll
            for (int fn = 0; fn < 4; fn++)
                LDSM4(b[fn], sx_base + sw128((uint32_t)(bRow + fn * 16) * 128 + kb + bKs));
            #pragma unroll
            for (int fm = 0; fm < 2; fm++)
                #pragma unroll
                for (int fn = 0; fn < 4; fn++) {
                    MMA16816(acc[fm][2 * fn],     a[fm], b[fn][0], b[fn][1]);
                    MMA16816(acc[fm][2 * fn + 1], a[fm], b[fn][2], b[fn][3]);
                }
        }
    }

    // ---- epilogue: fuse scale + bias ----
    const int m_base = out0 + wm * 32 + (lane >> 2);
    #pragma unroll
    for (int fm = 0; fm < 2; fm++) {
        const int m0 = m_base + fm * 16;
        const float s0 = scale[m0],     bi0 = bias[m0];
        const float s1 = scale[m0 + 8], bi1 = bias[m0 + 8];
        #pragma unroll
        for (int nf = 0; nf < 8; nf++) {
            const int t0 = wn * 64 + nf * 8 + (lane & 3) * 2;
            float* o = out + (size_t)t0 * OUT_F;
            o[m0]             = fmaf(acc[fm][nf][0], s0, bi0);
            o[OUT_F + m0]     = fmaf(acc[fm][nf][1], s0, bi0);
            o[m0 + 8]         = fmaf(acc[fm][nf][2], s1, bi1);
            o[OUT_F + m0 + 8] = fmaf(acc[fm][nf][3], s1, bi1);
        }
    }
}

// ---------------- launch ----------------
extern "C" void kernel_launch(void* const* d_in, const int* in_sizes, int n_in,
                              void* d_out, int out_size) {
    const float* x     = (const float*)d_in[0];
    const int*   qw    = (const int*)d_in[1];
    const float* scale = (const float*)d_in[2];
    const float* bias  = (const float*)d_in[3];
    float* out = (float*)d_out;

    prep_half_kernel<<<(TOKENS * IN_F / 2) / 256, 256>>>(x);

    cudaFuncSetAttribute(qlinear_kernel, cudaFuncAttributeMaxDynamicSharedMemorySize, SMEM_TOTAL);
    qlinear_kernel<<<NBLOCKS, NTHREADS, SMEM_TOTAL>>>(qw, scale, bias, out);
}

// round 7
// speedup vs baseline: 2.4242x; 1.1693x over previous
#include <cuda_runtime.h>
#include <cuda_fp16.h>
#include <cstdint>

// ---------------- problem constants ----------------
#define TOKENS 256
#define IN_F   4096
#define OUT_F  14336
#define KC     64
#define NCHUNK (IN_F / KC)        // 64
#define M_TILE 128
#define NTHREADS 512
#define NBLOCKS (OUT_F / M_TILE)  // 112

// ---------------- scratch ----------------
__device__ __half g_xh[TOKENS * IN_F];

// ---------------- smem layout ----------------
// per stage (128B rows): W 128x128B = 16384 | x 256x128B = 32768
#define STAGE_BYTES 49152
#define SM_W(s)     ((s) * STAGE_BYTES)
#define SM_X(s)     (SM_W(s) + 16384)
#define SMEM_TOTAL  (2 * STAGE_BYTES)   // 98304 B

// ---------------- helpers ----------------
__device__ __forceinline__ uint32_t smem_u32(const void* p) {
    uint32_t a;
    asm("{ .reg .u64 t; cvta.to.shared.u64 t, %1; cvt.u32.u64 %0, t; }" : "=r"(a) : "l"(p));
    return a;
}

// 128B-row swizzle: XOR bits[6:4] with bits[9:7]
__device__ __forceinline__ uint32_t sw128(uint32_t off) {
    return off ^ ((off >> 3) & 0x70);
}

__device__ __forceinline__ void cp_async16(uint32_t dst, const void* src) {
    asm volatile("cp.async.cg.shared.global [%0], [%1], 16;" :: "r"(dst), "l"(src));
}
#define CP_COMMIT()  asm volatile("cp.async.commit_group;" ::: "memory")
#define CP_WAIT0()   asm volatile("cp.async.wait_group 0;" ::: "memory")

#define LDSM4(R, addr)                                                              \
    asm volatile("ldmatrix.sync.aligned.m8n8.x4.shared.b16 {%0,%1,%2,%3}, [%4];"    \
        : "=r"((R)[0]), "=r"((R)[1]), "=r"((R)[2]), "=r"((R)[3]) : "r"(addr))

#define MMA16816(C, A, B0, B1)                                                      \
    asm volatile("mma.sync.aligned.m16n8k16.row.col.f32.f16.f16.f32 "               \
        "{%0,%1,%2,%3}, {%4,%5,%6,%7}, {%8,%9}, {%0,%1,%2,%3};"                     \
        : "+f"((C)[0]), "+f"((C)[1]), "+f"((C)[2]), "+f"((C)[3])                    \
        : "r"((A)[0]), "r"((A)[1]), "r"((A)[2]), "r"((A)[3]), "r"(B0), "r"(B1))

// ---------------- prep: x -> fp16 ----------------
__global__ void prep_half_kernel(const float* __restrict__ x) {
    int i = blockIdx.x * blockDim.x + threadIdx.x;
    float2 v = ((const float2*)x)[i];
    __half2 h;
    h.x = __float2half_rn(v.x);
    h.y = __float2half_rn(v.y);
    ((__half2*)g_xh)[i] = h;
}

// ---------------- main GEMM kernel ----------------
__global__ void __launch_bounds__(NTHREADS, 1)
qlinear_kernel(const int* __restrict__ qw, const float* __restrict__ scale,
               const float* __restrict__ bias, float* __restrict__ out) {
    extern __shared__ char smem[];
    const uint32_t sb = smem_u32(smem);
    const int tid  = threadIdx.x;
    const int lane = tid & 31;
    const int wid  = tid >> 5;
    const int wm   = wid & 3;   // 4 warps along M (32 rows each)
    const int wn   = wid >> 2;  // 4 warps along N (64 tokens each)
    const int out0 = blockIdx.x * M_TILE;

    // ---- W loader: thread t -> row t/4, ints [16q, 16q+16) of each chunk ----
    const int wrow = tid >> 2;      // 0..127
    const int wq   = tid & 3;
    const int4* wptr = (const int4*)(qw + (size_t)(out0 + wrow) * IN_F + wq * 16);
    const uint32_t w_sts0 = sw128((uint32_t)wrow * 128 + (uint32_t)wq * 32);
    const uint32_t w_sts1 = sw128((uint32_t)wrow * 128 + (uint32_t)wq * 32 + 16);

    const char* xh_b = (const char*)g_xh;

    // ---- ldmatrix base indices ----
    const int aRow = wm * 32 + (lane & 15);
    const int aKs  = (lane & 16) ? 16 : 0;
    const int bRow = wn * 64 + (lane & 7) + ((lane & 16) ? 8 : 0);
    const int bKs  = (lane & 8) ? 16 : 0;

#define AADDR(base, ks, fm) ((base) + sw128((uint32_t)(aRow + (fm) * 16) * 128 + (uint32_t)(ks) * 32 + aKs))
#define BADDR(base, ks, fn) ((base) + sw128((uint32_t)(bRow + (fn) * 16) * 128 + (uint32_t)(ks) * 32 + bKs))

    float acc[2][8][4];
    #pragma unroll
    for (int i = 0; i < 2; i++)
        #pragma unroll
        for (int j = 0; j < 8; j++)
            #pragma unroll
            for (int k = 0; k < 4; k++) acc[i][j][k] = 0.0f;

    int4 v0, v1, v2, v3;

    // ---- prologue ----
    {
        // x(0) -> stage0
        #pragma unroll
        for (int j = 0; j < 4; j++) {
            int u = tid + j * NTHREADS;          // 0..2047
            int row = u >> 3, c = u & 7;
            uint32_t d = sw128((uint32_t)row * 128 + (uint32_t)c * 16);
            size_t so = (size_t)row * (IN_F * 2) + (size_t)c * 16;
            cp_async16(sb + SM_X(0) + d, xh_b + so);
        }
        CP_COMMIT();
        // W(0) -> regs -> smem stage0
        v0 = wptr[0]; v1 = wptr[1]; v2 = wptr[2]; v3 = wptr[3];
        {
            __half2 h[8];
            h[0] = __halves2half2(__int2half_rn(v0.x), __int2half_rn(v0.y));
            h[1] = __halves2half2(__int2half_rn(v0.z), __int2half_rn(v0.w));
            h[2] = __halves2half2(__int2half_rn(v1.x), __int2half_rn(v1.y));
            h[3] = __halves2half2(__int2half_rn(v1.z), __int2half_rn(v1.w));
            h[4] = __halves2half2(__int2half_rn(v2.x), __int2half_rn(v2.y));
            h[5] = __halves2half2(__int2half_rn(v2.z), __int2half_rn(v2.w));
            h[6] = __halves2half2(__int2half_rn(v3.x), __int2half_rn(v3.y));
            h[7] = __halves2half2(__int2half_rn(v3.z), __int2half_rn(v3.w));
            uint32_t* p = (uint32_t*)h;
            asm volatile("st.shared.v4.b32 [%0], {%1,%2,%3,%4};"
                         :: "r"(sb + SM_W(0) + w_sts0), "r"(p[0]), "r"(p[1]), "r"(p[2]), "r"(p[3]) : "memory");
            asm volatile("st.shared.v4.b32 [%0], {%1,%2,%3,%4};"
                         :: "r"(sb + SM_W(0) + w_sts1), "r"(p[4]), "r"(p[5]), "r"(p[6]), "r"(p[7]) : "memory");
        }
        // W(1) -> regs
        v0 = wptr[16]; v1 = wptr[17]; v2 = wptr[18]; v3 = wptr[19];
        CP_WAIT0();
        __syncthreads();
    }

    for (int i = 0; i < NCHUNK; i++) {
        const int s = i & 1;
        const uint32_t sw_base = sb + SM_W(s);
        const uint32_t sx_base = sb + SM_X(s);
        const uint32_t swn_base = sb + SM_W(s ^ 1);
        const uint32_t sxn_base = sb + SM_X(s ^ 1);

        uint32_t bf[2][4];
        uint32_t af0[4], af1[4];

        // preload B(step 0)
        LDSM4(bf[0], BADDR(sx_base, 0, 0));

        #pragma unroll
        for (int ks = 0; ks < 4; ks++) {
            LDSM4(af0, AADDR(sw_base, ks, 0));
            LDSM4(af1, AADDR(sw_base, ks, 1));
            #pragma unroll
            for (int fn = 0; fn < 4; fn++) {
                const int st = ks * 4 + fn;
                // prefetch next step's B between MMA groups
                if (st < 15) {
                    const int ns = st + 1;
                    LDSM4(bf[ns & 1], BADDR(sx_base, ns >> 2, ns & 3));
                }
                const uint32_t* bb = bf[st & 1];
                MMA16816(acc[0][2 * fn],     af0, bb[0], bb[1]);
                MMA16816(acc[0][2 * fn + 1], af0, bb[2], bb[3]);
                MMA16816(acc[1][2 * fn],     af1, bb[0], bb[1]);
                MMA16816(acc[1][2 * fn + 1], af1, bb[2], bb[3]);
            }

            // chunk-level memory work, hoisted into the compute region
            if (ks == 0 && i + 1 < NCHUNK) {
                // x(i+1) -> other stage
                const size_t co = (size_t)(i + 1) * (KC * 2);
                #pragma unroll
                for (int j = 0; j < 4; j++) {
                    int u = tid + j * NTHREADS;
                    int row = u >> 3, c = u & 7;
                    uint32_t d = sw128((uint32_t)row * 128 + (uint32_t)c * 16);
                    size_t so = (size_t)row * (IN_F * 2) + co + (size_t)c * 16;
                    cp_async16(sxn_base + d, xh_b + so);
                }
                CP_COMMIT();
                // convert + STS W(i+1) -> other stage
                {
                    __half2 h[8];
                    h[0] = __halves2half2(__int2half_rn(v0.x), __int2half_rn(v0.y));
                    h[1] = __halves2half2(__int2half_rn(v0.z), __int2half_rn(v0.w));
                    h[2] = __halves2half2(__int2half_rn(v1.x), __int2half_rn(v1.y));
                    h[3] = __halves2half2(__int2half_rn(v1.z), __int2half_rn(v1.w));
                    h[4] = __halves2half2(__int2half_rn(v2.x), __int2half_rn(v2.y));
                    h[5] = __halves2half2(__int2half_rn(v2.z), __int2half_rn(v2.w));
                    h[6] = __halves2half2(__int2half_rn(v3.x), __int2half_rn(v3.y));
                    h[7] = __halves2half2(__int2half_rn(v3.z), __int2half_rn(v3.w));
                    uint32_t* p = (uint32_t*)h;
                    asm volatile("st.shared.v4.b32 [%0], {%1,%2,%3,%4};"
                                 :: "r"(swn_base + w_sts0), "r"(p[0]), "r"(p[1]), "r"(p[2]), "r"(p[3]) : "memory");
                    asm volatile("st.shared.v4.b32 [%0], {%1,%2,%3,%4};"
                                 :: "r"(swn_base + w_sts1), "r"(p[4]), "r"(p[5]), "r"(p[6]), "r"(p[7]) : "memory");
                }
                // LDG W(i+2)
                if (i + 2 < NCHUNK) {
                    const int4* wnp = wptr + (size_t)(i + 2) * 16;
                    v0 = wnp[0]; v1 = wnp[1]; v2 = wnp[2]; v3 = wnp[3];
                }
            }
        }

        CP_WAIT0();
        __syncthreads();
    }

    // ---- epilogue: fuse scale + bias ----
    const int m_base = out0 + wm * 32 + (lane >> 2);
    #pragma unroll
    for (int fm = 0; fm < 2; fm++) {
        const int m0 = m_base + fm * 16;
        const float s0 = scale[m0],     bi0 = bias[m0];
        const float s1 = scale[m0 + 8], bi1 = bias[m0 + 8];
        #pragma unroll
        for (int nf = 0; nf < 8; nf++) {
            const int t0 = wn * 64 + nf * 8 + (lane & 3) * 2;
            float* o = out + (size_t)t0 * OUT_F;
            o[m0]             = fmaf(acc[fm][nf][0], s0, bi0);
            o[OUT_F + m0]     = fmaf(acc[fm][nf][1], s0, bi0);
            o[m0 + 8]         = fmaf(acc[fm][nf][2], s1, bi1);
            o[OUT_F + m0 + 8] = fmaf(acc[fm][nf][3], s1, bi1);
        }
    }
}

// ---------------- launch ----------------
extern "C" void kernel_launch(void* const* d_in, const int* in_sizes, int n_in,
                              void* d_out, int out_size) {
    const float* x     = (const float*)d_in[0];
    const int*   qw    = (const int*)d_in[1];
    const float* scale = (const float*)d_in[2];
    const float* bias  = (const float*)d_in[3];
    float* out = (float*)d_out;

    prep_half_kernel<<<(TOKENS * IN_F / 2) / 256, 256>>>(x);

    cudaFuncSetAttribute(qlinear_kernel, cudaFuncAttributeMaxDynamicSharedMemorySize, SMEM_TOTAL);
    qlinear_kernel<<<NBLOCKS, NTHREADS, SMEM_TOTAL>>>(qw, scale, bias, out);
}